// round 14
// baseline (speedup 1.0000x reference)
#include <cuda_runtime.h>
#include <cuda_fp16.h>
#include <cstdint>

// Problem constants (fixed by dataset: B=4, S=2048, D=1024, O=1024, C=8)
#define T_TOK 8192
#define DIM_D 1024
#define DIM_O 1024
#define N_CAT 8

#define TM 128
#define TN 128
#define BK 64                        // K per smem stage
#define NCHUNK (DIM_D / BK)          // 16
#define MAX_TILES (T_TOK / TM + N_CAT)   // 72
#define N_GEMM_BLK (MAX_TILES * (DIM_O / TN))  // 576

// block ranges inside the fused grid
#define BLK_SETUP   0
#define BLK_X0      1
#define BLK_XN      4096
#define BLK_W0      (BLK_X0 + BLK_XN)          // 4097
#define BLK_WN      4096
#define BLK_GEMM0   (BLK_W0 + BLK_WN)          // 8193
#define GRID_TOTAL  (BLK_GEMM0 + N_GEMM_BLK)   // 8769

// ---------------- device scratch (no allocation allowed) --------------------
__device__ int g_perm[T_TOK];
__device__ int g_tile_cat[MAX_TILES];
__device__ int g_tile_row[MAX_TILES];
__device__ int g_tile_rows[MAX_TILES];
__device__ int g_n_tiles;

// progress flags (zero at module load; reset by last GEMM block every launch)
__device__ int g_setup_done;
__device__ int g_xcnt;
__device__ int g_wcnt[N_CAT];
__device__ int g_done;

// fp16 operands. X in NATURAL token order (+TM zero pad rows, never written).
__device__ __half g_Xh[(T_TOK + TM) * DIM_D];
__device__ __half g_Wh[N_CAT * DIM_D * DIM_O];   // [c][d][o]

// ---------------- PTX helpers (baseline sm_70/75/80 features only) ----------
__device__ __forceinline__ uint32_t smem_u32(const void* p) {
    uint32_t a;
    asm("{ .reg .u64 t; cvta.to.shared.u64 t, %1; cvt.u32.u64 %0, t; }" : "=r"(a) : "l"(p));
    return a;
}

__device__ __forceinline__ int ld_acq(const int* p) {
    int v;
    asm volatile("ld.acquire.gpu.s32 %0, [%1];" : "=r"(v) : "l"(p) : "memory");
    return v;
}

#define CP_ASYNC16(dst, src) \
    asm volatile("cp.async.cg.shared.global [%0], [%1], 16;" :: "r"(dst), "l"(src) : "memory")
#define CP_COMMIT() asm volatile("cp.async.commit_group;" ::: "memory")
#define CP_WAIT0()  asm volatile("cp.async.wait_group 0;" ::: "memory")
#define CP_WAIT1()  asm volatile("cp.async.wait_group 1;" ::: "memory")

#define LDSM4(r0, r1, r2, r3, addr)                                              \
    asm volatile("ldmatrix.sync.aligned.m8n8.x4.shared.b16 {%0,%1,%2,%3}, [%4];" \
                 : "=r"(r0), "=r"(r1), "=r"(r2), "=r"(r3) : "r"(addr))

#define LDSM4T(r0, r1, r2, r3, addr)                                                   \
    asm volatile("ldmatrix.sync.aligned.m8n8.x4.trans.shared.b16 {%0,%1,%2,%3}, [%4];" \
                 : "=r"(r0), "=r"(r1), "=r"(r2), "=r"(r3) : "r"(addr))

#define MMA_F16(c, a, b)                                                         \
    asm volatile("mma.sync.aligned.m16n8k16.row.col.f32.f16.f16.f32 "            \
                 "{%0,%1,%2,%3}, {%4,%5,%6,%7}, {%8,%9}, {%0,%1,%2,%3};"         \
                 : "+f"((c)[0]), "+f"((c)[1]), "+f"((c)[2]), "+f"((c)[3])        \
                 : "r"((a)[0]), "r"((a)[1]), "r"((a)[2]), "r"((a)[3]),           \
                   "r"((b)[0]), "r"((b)[1]))

__device__ __forceinline__ uint32_t sw128(uint32_t off) {
    return off ^ ((off >> 3) & 0x70);
}

// smem layout for the GEMM path
#define SM_TOKS   0
#define SM_BIAS   512
#define SM_STAGE  2048
#define PART_A_BYTES 16384
#define STAGE_BYTES  32768
#define NSTAGE 3
#define SMEM_TOTAL (SM_STAGE + NSTAGE * STAGE_BYTES)

// ---------------- fused kernel ----------------------------------------------
__global__ __launch_bounds__(256, 2)
void k_fused(const int* __restrict__ cid,
             const float* __restrict__ w,
             const float* __restrict__ x,
             const float* __restrict__ bias,
             float* __restrict__ out) {
    const int b   = blockIdx.x;
    const int tid = threadIdx.x;    // 256

    // ================= setup block ==========================================
    if (b == BLK_SETUP) {
        __shared__ int s_cnt[N_CAT][256];
        __shared__ int s_exc[N_CAT][256];
        __shared__ int s_base[N_CAT];

        int cl[32];
        uint32_t p0 = 0, p1 = 0;
#pragma unroll
        for (int i = 0; i < 32; i++) {
            int c = cid[tid + i * 256] & (N_CAT - 1);
            cl[i] = c;
            if (c < 4) p0 += 1u << (c * 8); else p1 += 1u << ((c - 4) * 8);
        }
#pragma unroll
        for (int c = 0; c < 4; c++) {
            s_cnt[c][tid]     = (p0 >> (c * 8)) & 0xFF;
            s_cnt[c + 4][tid] = (p1 >> (c * 8)) & 0xFF;
        }
        __syncthreads();

        const int wid = tid >> 5, lane = tid & 31;
        {
            int run = 0;
#pragma unroll
            for (int ch = 0; ch < 8; ch++) {
                int v0 = s_cnt[wid][ch * 32 + lane];
                int v = v0;
#pragma unroll
                for (int o = 1; o < 32; o <<= 1) {
                    int n = __shfl_up_sync(0xFFFFFFFFu, v, o);
                    if (lane >= o) v += n;
                }
                s_exc[wid][ch * 32 + lane] = run + v - v0;
                run += __shfl_sync(0xFFFFFFFFu, v, 31);
            }
            if (lane == 0) s_base[wid] = run;   // temp: per-cat totals
        }
        __syncthreads();

        if (tid == 0) {
            int off = 0, nt = 0;
            for (int c = 0; c < N_CAT; c++) {
                int cnt = s_base[c];
                s_base[c] = off;
                for (int r = 0; r < cnt; r += TM) {
                    g_tile_cat[nt]  = c;
                    g_tile_row[nt]  = off + r;
                    g_tile_rows[nt] = (cnt - r < TM) ? (cnt - r) : TM;
                    nt++;
                }
                off += cnt;
            }
            g_n_tiles = nt;
        }
        __syncthreads();

        p0 = 0; p1 = 0;
#pragma unroll
        for (int i = 0; i < 32; i++) {
            int c = cl[i];
            int run = (c < 4) ? ((p0 >> (c * 8)) & 0xFF) : ((p1 >> ((c - 4) * 8)) & 0xFF);
            g_perm[s_base[c] + s_exc[c][tid] + run] = tid + i * 256;
            if (c < 4) p0 += 1u << (c * 8); else p1 += 1u << ((c - 4) * 8);
        }

        __threadfence();
        __syncthreads();
        if (tid == 0) atomicExch(&g_setup_done, 1);
        return;
    }

    // ================= X convert blocks =====================================
    if (b <= BLK_XN) {
        const size_t base = (size_t)(b - BLK_X0) * 2048;
#pragma unroll
        for (int j = 0; j < 2; j++) {
            const size_t i = base + (size_t)(tid + j * 256) * 4;
            float4 v = *reinterpret_cast<const float4*>(x + i);
            __half2 h0 = __floats2half2_rn(v.x, v.y);
            __half2 h1 = __floats2half2_rn(v.z, v.w);
            uint2 u;
            u.x = *reinterpret_cast<uint32_t*>(&h0);
            u.y = *reinterpret_cast<uint32_t*>(&h1);
            *reinterpret_cast<uint2*>(&g_Xh[i]) = u;
        }
        __threadfence();
        __syncthreads();
        if (tid == 0) atomicAdd(&g_xcnt, 1);
        return;
    }

    // ================= W convert blocks (ordered by category) ===============
    if (b < BLK_GEMM0) {
        const int wb = b - BLK_W0;          // 0..4095; cat = wb >> 9
        const size_t base = (size_t)wb * 2048;
#pragma unroll
        for (int j = 0; j < 2; j++) {
            const size_t i = base + (size_t)(tid + j * 256) * 4;
            float4 v = *reinterpret_cast<const float4*>(w + i);
            __half2 h0 = __floats2half2_rn(v.x, v.y);
            __half2 h1 = __floats2half2_rn(v.z, v.w);
            uint2 u;
            u.x = *reinterpret_cast<uint32_t*>(&h0);
            u.y = *reinterpret_cast<uint32_t*>(&h1);
            *reinterpret_cast<uint2*>(&g_Wh[i]) = u;
        }
        __threadfence();
        __syncthreads();
        if (tid == 0) atomicAdd(&g_wcnt[wb >> 9], 1);
        return;
    }

    // ================= GEMM blocks ==========================================
    const int g    = b - BLK_GEMM0;       // 0..575
    const int tile = g >> 3;              // 0..71 (ordered by category)
    const int n0   = (g & 7) * TN;

    // wait: setup done (tile descriptors + perm valid)
    while (ld_acq(&g_setup_done) == 0) __nanosleep(128);

    if (tile >= g_n_tiles) {
        __syncthreads();
        if (tid == 0) {
            int old = atomicAdd(&g_done, 1);
            if (old == N_GEMM_BLK - 1) {       // last one resets for next launch
                g_setup_done = 0; g_xcnt = 0; g_done = 0;
                for (int c = 0; c < N_CAT; c++) g_wcnt[c] = 0;
                __threadfence();
            }
        }
        return;
    }

    const int cat       = g_tile_cat[tile] & (N_CAT - 1);
    const int row_start = g_tile_row[tile];
    const int rows      = g_tile_rows[tile];

    // wait: all X converted, this category's W converted
    while (ld_acq(&g_xcnt) < BLK_XN) __nanosleep(128);
    while (ld_acq(&g_wcnt[cat]) < 512) __nanosleep(128);

    extern __shared__ char smem[];
    const uint32_t sm = smem_u32(smem);
    const int wid  = tid >> 5;
    const int lane = tid & 31;
    const int wm   = wid >> 2;        // 0..1 -> m offset wm*64
    const int wn   = wid & 3;         // 0..3 -> n offset wn*32

    int*   toks   = reinterpret_cast<int*>(smem + SM_TOKS);
    float* bias_s = reinterpret_cast<float*>(smem + SM_BIAS);
    if (tid < TM) toks[tid] = (tid < rows) ? g_perm[row_start + tid] : -1;
    if (tid >= 128) bias_s[tid - 128] = bias[cat * DIM_O + n0 + tid - 128];
    __syncthreads();

    // A row pointers (gathered; chunk-invariant). Padding -> zero pad row.
    const char* aRow[4];
#pragma unroll
    for (int t = 0; t < 4; t++) {
        int r   = (tid >> 3) + t * 32;
        int tok = toks[r];
        if (tok < 0) tok = T_TOK + r;   // zero pad row
        aRow[t] = reinterpret_cast<const char*>(g_Xh) + (size_t)tok * 2048 + (tid & 7) * 16;
    }
    const char* gB = reinterpret_cast<const char*>(g_Wh) + (((size_t)cat << 20) + n0) * 2;

#define ISSUE_CHUNK(kc, buf)                                                        \
    _Pragma("unroll")                                                               \
    for (int t = 0; t < 8; t++) {                                                   \
        uint32_t stg = sm + SM_STAGE + (buf) * STAGE_BYTES;                         \
        if (t < 4) {                                                                \
            int r = (tid >> 3) + t * 32, c = tid & 7;                               \
            const char* src = aRow[t] + (size_t)(kc) * 128;                         \
            CP_ASYNC16(stg + sw128((uint32_t)(r * 128 + c * 16)), src);             \
        } else {                                                                    \
            int i2 = tid + (t - 4) * 256;                                           \
            int r = i2 >> 4, c = i2 & 15;                                           \
            const char* src = gB + (size_t)((kc) * BK + r) * 2048 + c * 16;         \
            CP_ASYNC16(stg + PART_A_BYTES + (uint32_t)(r * 256 + ((c ^ (r & 7)) * 16)), src); \
        }                                                                           \
    }                                                                               \
    CP_COMMIT();

    float acc[4][4][4];
#pragma unroll
    for (int i = 0; i < 4; i++)
#pragma unroll
        for (int j = 0; j < 4; j++)
#pragma unroll
            for (int k = 0; k < 4; k++) acc[i][j][k] = 0.f;

    ISSUE_CHUNK(0, 0);
    ISSUE_CHUNK(1, 1);

    const int fr_row = lane & 15;
    const int fr_kb  = lane >> 4;
    const int bk_loc = (lane & 7) + ((lane >> 3) & 1) * 8;   // 0..15
    const int bn_blk = (lane >> 4);                           // 0/1 -> +8 n

    for (int it = 0; it < NCHUNK; it++) {
        if (it < NCHUNK - 1) { CP_WAIT1(); } else { CP_WAIT0(); }
        __syncthreads();

        if (it + 2 < NCHUNK) { ISSUE_CHUNK(it + 2, (it + 2) % NSTAGE); }

        const uint32_t st  = sm + SM_STAGE + (it % NSTAGE) * STAGE_BYTES;
        const uint32_t stA = st;
        const uint32_t stB = st + PART_A_BYTES;

#pragma unroll
        for (int ks = 0; ks < 4; ks++) {
            const uint32_t kcol = (uint32_t)((ks * 2 + fr_kb) * 16);

            uint32_t a[4][4], bb[4][2];
#pragma unroll
            for (int mi = 0; mi < 4; mi++) {
                uint32_t ad = sw128((uint32_t)((wm * 64 + mi * 16 + fr_row) * 128) + kcol);
                LDSM4(a[mi][0], a[mi][1], a[mi][2], a[mi][3], stA + ad);
            }
#pragma unroll
            for (int pj = 0; pj < 2; pj++) {
                int k   = ks * 16 + bk_loc;
                int blk = wn * 4 + pj * 2 + bn_blk;
                uint32_t ad = (uint32_t)(k * 256 + ((blk ^ (k & 7)) * 16));
                uint32_t r0, r1, r2, r3;
                LDSM4T(r0, r1, r2, r3, stB + ad);
                bb[pj * 2][0]     = r0; bb[pj * 2][1]     = r1;
                bb[pj * 2 + 1][0] = r2; bb[pj * 2 + 1][1] = r3;
            }

#pragma unroll
            for (int mi = 0; mi < 4; mi++)
#pragma unroll
                for (int ni = 0; ni < 4; ni++)
                    MMA_F16(acc[mi][ni], a[mi], bb[ni]);
        }
    }

    // ---- epilogue: bias + scatter
#pragma unroll
    for (int mi = 0; mi < 4; mi++) {
        int m0   = wm * 64 + mi * 16 + (lane >> 2);
        int tok0 = toks[m0];
        int tok1 = toks[m0 + 8];
#pragma unroll
        for (int ni = 0; ni < 4; ni++) {
            int col = wn * 32 + ni * 8 + 2 * (lane & 3);
            float b0 = bias_s[col], b1 = bias_s[col + 1];
            if (tok0 >= 0) {
                float2 v = make_float2(acc[mi][ni][0] + b0, acc[mi][ni][1] + b1);
                *reinterpret_cast<float2*>(out + (size_t)tok0 * DIM_O + n0 + col) = v;
            }
            if (tok1 >= 0) {
                float2 v = make_float2(acc[mi][ni][2] + b0, acc[mi][ni][3] + b1);
                *reinterpret_cast<float2*>(out + (size_t)tok1 * DIM_O + n0 + col) = v;
            }
        }
    }

    __syncthreads();
    if (tid == 0) {
        int old = atomicAdd(&g_done, 1);
        if (old == N_GEMM_BLK - 1) {           // last GEMM block resets flags
            g_setup_done = 0; g_xcnt = 0; g_done = 0;
            for (int c = 0; c < N_CAT; c++) g_wcnt[c] = 0;
            __threadfence();
        }
    }
}

// ---------------- launch --------------------------------------------------------
extern "C" void kernel_launch(void* const* d_in, const int* in_sizes, int n_in,
                              void* d_out, int out_size) {
    const float* x    = (const float*)d_in[0];   // [T, D] fp32
    const int*   cid  = (const int*)d_in[1];     // [T] int32
    const float* wgt  = (const float*)d_in[2];   // [C, D, O] fp32
    const float* bias = (const float*)d_in[3];   // [C, O] fp32
    float*       out  = (float*)d_out;           // [T, O] fp32

    (void)in_sizes; (void)n_in; (void)out_size;

    cudaFuncSetAttribute(k_fused, cudaFuncAttributeMaxDynamicSharedMemorySize, SMEM_TOTAL);

    k_fused<<<GRID_TOTAL, 256, SMEM_TOTAL>>>(cid, wgt, x, bias, out);
}

// round 15
// speedup vs baseline: 1.6964x; 1.6964x over previous
#include <cuda_runtime.h>
#include <cuda_fp16.h>
#include <cstdint>

// Problem constants (fixed by dataset: B=4, S=2048, D=1024, O=1024, C=8)
#define T_TOK 8192
#define DIM_D 1024
#define DIM_O 1024
#define N_CAT 8

#define TM 128
#define TN 128
#define BK 64                        // K per smem stage
#define NCHUNK (DIM_D / BK)          // 16
#define MAX_TILES (T_TOK / TM + N_CAT)          // 72
#define N_GEMM_TK (MAX_TILES * (DIM_O / TN))    // 576

#define NBLK 296                     // persistent blocks (2 per SM target)
#define UNIT_FLOATS 16384
#define X_UNITS 512                  // 8.39M floats
#define W_UNITS 512
#define CONV_UNITS (X_UNITS + W_UNITS)

// ---------------- device scratch (no allocation allowed) --------------------
__device__ int g_perm[T_TOK];
__device__ int g_tile_cat[MAX_TILES];
__device__ int g_tile_row[MAX_TILES];
__device__ int g_tile_rows[MAX_TILES];
__device__ int g_n_tiles;

// progress state (zero at module load; reset by last exiting block each launch)
__device__ int g_setup_done;
__device__ int g_tk_conv;
__device__ int g_xdone;
__device__ int g_wdone[N_CAT];
__device__ int g_tk_gemm;
__device__ int g_exit;

// fp16 operands. X in NATURAL token order (+TM zero pad rows, never written).
__device__ __half g_Xh[(T_TOK + TM) * DIM_D];
__device__ __half g_Wh[N_CAT * DIM_D * DIM_O];   // [c][d][o]

// ---------------- PTX helpers (baseline sm_70/75/80 features only) ----------
__device__ __forceinline__ uint32_t smem_u32(const void* p) {
    uint32_t a;
    asm("{ .reg .u64 t; cvta.to.shared.u64 t, %1; cvt.u32.u64 %0, t; }" : "=r"(a) : "l"(p));
    return a;
}

__device__ __forceinline__ int ld_acq(const int* p) {
    int v;
    asm volatile("ld.acquire.gpu.s32 %0, [%1];" : "=r"(v) : "l"(p) : "memory");
    return v;
}

#define CP_ASYNC16(dst, src) \
    asm volatile("cp.async.cg.shared.global [%0], [%1], 16;" :: "r"(dst), "l"(src) : "memory")
#define CP_COMMIT() asm volatile("cp.async.commit_group;" ::: "memory")
#define CP_WAIT0()  asm volatile("cp.async.wait_group 0;" ::: "memory")
#define CP_WAIT1()  asm volatile("cp.async.wait_group 1;" ::: "memory")

#define LDSM4(r0, r1, r2, r3, addr)                                              \
    asm volatile("ldmatrix.sync.aligned.m8n8.x4.shared.b16 {%0,%1,%2,%3}, [%4];" \
                 : "=r"(r0), "=r"(r1), "=r"(r2), "=r"(r3) : "r"(addr))

#define LDSM4T(r0, r1, r2, r3, addr)                                                   \
    asm volatile("ldmatrix.sync.aligned.m8n8.x4.trans.shared.b16 {%0,%1,%2,%3}, [%4];" \
                 : "=r"(r0), "=r"(r1), "=r"(r2), "=r"(r3) : "r"(addr))

#define MMA_F16(c, a, b)                                                         \
    asm volatile("mma.sync.aligned.m16n8k16.row.col.f32.f16.f16.f32 "            \
                 "{%0,%1,%2,%3}, {%4,%5,%6,%7}, {%8,%9}, {%0,%1,%2,%3};"         \
                 : "+f"((c)[0]), "+f"((c)[1]), "+f"((c)[2]), "+f"((c)[3])        \
                 : "r"((a)[0]), "r"((a)[1]), "r"((a)[2]), "r"((a)[3]),           \
                   "r"((b)[0]), "r"((b)[1]))

__device__ __forceinline__ uint32_t sw128(uint32_t off) {
    return off ^ ((off >> 3) & 0x70);
}

// smem layout for the GEMM phase
#define SM_TOKS   0
#define SM_BIAS   512
#define SM_STAGE  2048
#define PART_A_BYTES 16384
#define STAGE_BYTES  32768
#define NSTAGE 3
#define SMEM_TOTAL (SM_STAGE + NSTAGE * STAGE_BYTES)

// ---------------- persistent fused kernel ------------------------------------
__global__ __launch_bounds__(256, 2)
void k_persist(const int* __restrict__ cid,
               const float* __restrict__ w,
               const float* __restrict__ x,
               const float* __restrict__ bias,
               float* __restrict__ out) {
    extern __shared__ char smem[];
    __shared__ int s_tk;
    const int tid = threadIdx.x;    // 256
    const uint32_t sm = smem_u32(smem);

    // ================= setup (block 0 only; others start converting) ========
    if (blockIdx.x == 0) {
        int (*s_cnt)[256] = reinterpret_cast<int (*)[256]>(smem);          // 8KB
        int (*s_exc)[256] = reinterpret_cast<int (*)[256]>(smem + 8192);   // 8KB
        int* s_base       = reinterpret_cast<int*>(smem + 16384);

        int cl[32];
        uint32_t p0 = 0, p1 = 0;
#pragma unroll
        for (int i = 0; i < 32; i++) {
            int c = cid[tid + i * 256] & (N_CAT - 1);
            cl[i] = c;
            if (c < 4) p0 += 1u << (c * 8); else p1 += 1u << ((c - 4) * 8);
        }
#pragma unroll
        for (int c = 0; c < 4; c++) {
            s_cnt[c][tid]     = (p0 >> (c * 8)) & 0xFF;
            s_cnt[c + 4][tid] = (p1 >> (c * 8)) & 0xFF;
        }
        __syncthreads();

        const int wd = tid >> 5, lane = tid & 31;
        {
            int run = 0;
#pragma unroll
            for (int ch = 0; ch < 8; ch++) {
                int v0 = s_cnt[wd][ch * 32 + lane];
                int v = v0;
#pragma unroll
                for (int o = 1; o < 32; o <<= 1) {
                    int n = __shfl_up_sync(0xFFFFFFFFu, v, o);
                    if (lane >= o) v += n;
                }
                s_exc[wd][ch * 32 + lane] = run + v - v0;
                run += __shfl_sync(0xFFFFFFFFu, v, 31);
            }
            if (lane == 0) s_base[wd] = run;
        }
        __syncthreads();

        if (tid == 0) {
            int off = 0, nt = 0;
            for (int c = 0; c < N_CAT; c++) {
                int cnt = s_base[c];
                s_base[c] = off;
                for (int r = 0; r < cnt; r += TM) {
                    g_tile_cat[nt]  = c;
                    g_tile_row[nt]  = off + r;
                    g_tile_rows[nt] = (cnt - r < TM) ? (cnt - r) : TM;
                    nt++;
                }
                off += cnt;
            }
            g_n_tiles = nt;
        }
        __syncthreads();

        p0 = 0; p1 = 0;
#pragma unroll
        for (int i = 0; i < 32; i++) {
            int c = cl[i];
            int run = (c < 4) ? ((p0 >> (c * 8)) & 0xFF) : ((p1 >> ((c - 4) * 8)) & 0xFF);
            g_perm[s_base[c] + s_exc[c][tid] + run] = tid + i * 256;
            if (c < 4) p0 += 1u << (c * 8); else p1 += 1u << ((c - 4) * 8);
        }

        __threadfence();
        __syncthreads();
        if (tid == 0) atomicExch(&g_setup_done, 1);
        __syncthreads();
    }

    // ================= convert phase: work-steal units =======================
    for (;;) {
        if (tid == 0) s_tk = atomicAdd(&g_tk_conv, 1);
        __syncthreads();
        const int u = s_tk;
        if (u >= CONV_UNITS) break;

        if (u < X_UNITS) {
            const size_t base = (size_t)u * UNIT_FLOATS;
#pragma unroll
            for (int j = 0; j < 16; j++) {
                const size_t i = base + (size_t)(j * 256 + tid) * 4;
                float4 v = *reinterpret_cast<const float4*>(x + i);
                __half2 h0 = __floats2half2_rn(v.x, v.y);
                __half2 h1 = __floats2half2_rn(v.z, v.w);
                uint2 uu;
                uu.x = *reinterpret_cast<uint32_t*>(&h0);
                uu.y = *reinterpret_cast<uint32_t*>(&h1);
                *reinterpret_cast<uint2*>(&g_Xh[i]) = uu;
            }
        } else {
            const int wu = u - X_UNITS;
            const size_t base = (size_t)wu * UNIT_FLOATS;
#pragma unroll
            for (int j = 0; j < 16; j++) {
                const size_t i = base + (size_t)(j * 256 + tid) * 4;
                float4 v = *reinterpret_cast<const float4*>(w + i);
                __half2 h0 = __floats2half2_rn(v.x, v.y);
                __half2 h1 = __floats2half2_rn(v.z, v.w);
                uint2 uu;
                uu.x = *reinterpret_cast<uint32_t*>(&h0);
                uu.y = *reinterpret_cast<uint32_t*>(&h1);
                *reinterpret_cast<uint2*>(&g_Wh[i]) = uu;
            }
        }
        __threadfence();
        __syncthreads();
        if (tid == 0) {
            if (u < X_UNITS) atomicAdd(&g_xdone, 1);
            else             atomicAdd(&g_wdone[(u - X_UNITS) >> 6], 1);
        }
    }

    // ================= GEMM phase: work-steal tiles ===========================
    const int wid  = tid >> 5;
    const int lane = tid & 31;
    const int wm   = wid >> 2;        // 0..1 -> m offset wm*64
    const int wn   = wid & 3;         // 0..3 -> n offset wn*32
    const int fr_row = lane & 15;
    const int fr_kb  = lane >> 4;
    const int bk_loc = (lane & 7) + ((lane >> 3) & 1) * 8;
    const int bn_blk = (lane >> 4);

    int*   toks   = reinterpret_cast<int*>(smem + SM_TOKS);
    float* bias_s = reinterpret_cast<float*>(smem + SM_BIAS);

    // setup must be done before reading tile descriptors
    while (ld_acq(&g_setup_done) == 0) __nanosleep(64);

    for (;;) {
        __syncthreads();   // protect smem (toks/bias/stages) reuse across tiles
        if (tid == 0) s_tk = atomicAdd(&g_tk_gemm, 1);
        __syncthreads();
        const int t = s_tk;
        if (t >= N_GEMM_TK) break;

        const int tile = t >> 3;
        const int n0   = (t & 7) * TN;
        if (tile >= g_n_tiles) continue;

        const int cat       = g_tile_cat[tile] & (N_CAT - 1);
        const int row_start = g_tile_row[tile];
        const int rows      = g_tile_rows[tile];

        // dependencies: all X units, this category's W units
        while (ld_acq(&g_xdone) < X_UNITS) __nanosleep(64);
        while (ld_acq(&g_wdone[cat]) < 64) __nanosleep(64);

        if (tid < TM) toks[tid] = (tid < rows) ? g_perm[row_start + tid] : -1;
        if (tid >= 128) bias_s[tid - 128] = bias[cat * DIM_O + n0 + tid - 128];
        __syncthreads();

        // A row pointers (gathered; chunk-invariant). Padding -> zero pad row.
        const char* aRow[4];
#pragma unroll
        for (int tt = 0; tt < 4; tt++) {
            int r   = (tid >> 3) + tt * 32;
            int tok = toks[r];
            if (tok < 0) tok = T_TOK + r;
            aRow[tt] = reinterpret_cast<const char*>(g_Xh) + (size_t)tok * 2048 + (tid & 7) * 16;
        }
        const char* gB = reinterpret_cast<const char*>(g_Wh) + (((size_t)cat << 20) + n0) * 2;

#define ISSUE_CHUNK(kc, buf)                                                        \
    _Pragma("unroll")                                                               \
    for (int q = 0; q < 8; q++) {                                                   \
        uint32_t stg = sm + SM_STAGE + (buf) * STAGE_BYTES;                         \
        if (q < 4) {                                                                \
            int r = (tid >> 3) + q * 32, c = tid & 7;                               \
            const char* src = aRow[q] + (size_t)(kc) * 128;                         \
            CP_ASYNC16(stg + sw128((uint32_t)(r * 128 + c * 16)), src);             \
        } else {                                                                    \
            int i2 = tid + (q - 4) * 256;                                           \
            int r = i2 >> 4, c = i2 & 15;                                           \
            const char* src = gB + (size_t)((kc) * BK + r) * 2048 + c * 16;         \
            CP_ASYNC16(stg + PART_A_BYTES + (uint32_t)(r * 256 + ((c ^ (r & 7)) * 16)), src); \
        }                                                                           \
    }                                                                               \
    CP_COMMIT();

        float acc[4][4][4];
#pragma unroll
        for (int i = 0; i < 4; i++)
#pragma unroll
            for (int j = 0; j < 4; j++)
#pragma unroll
                for (int k = 0; k < 4; k++) acc[i][j][k] = 0.f;

        ISSUE_CHUNK(0, 0);
        ISSUE_CHUNK(1, 1);

        for (int it = 0; it < NCHUNK; it++) {
            if (it < NCHUNK - 1) { CP_WAIT1(); } else { CP_WAIT0(); }
            __syncthreads();

            if (it + 2 < NCHUNK) { ISSUE_CHUNK(it + 2, (it + 2) % NSTAGE); }

            const uint32_t st  = sm + SM_STAGE + (it % NSTAGE) * STAGE_BYTES;
            const uint32_t stA = st;
            const uint32_t stB = st + PART_A_BYTES;

#pragma unroll
            for (int ks = 0; ks < 4; ks++) {
                const uint32_t kcol = (uint32_t)((ks * 2 + fr_kb) * 16);

                uint32_t a[4][4], bb[4][2];
#pragma unroll
                for (int mi = 0; mi < 4; mi++) {
                    uint32_t ad = sw128((uint32_t)((wm * 64 + mi * 16 + fr_row) * 128) + kcol);
                    LDSM4(a[mi][0], a[mi][1], a[mi][2], a[mi][3], stA + ad);
                }
#pragma unroll
                for (int pj = 0; pj < 2; pj++) {
                    int k   = ks * 16 + bk_loc;
                    int blk = wn * 4 + pj * 2 + bn_blk;
                    uint32_t ad = (uint32_t)(k * 256 + ((blk ^ (k & 7)) * 16));
                    uint32_t r0, r1, r2, r3;
                    LDSM4T(r0, r1, r2, r3, stB + ad);
                    bb[pj * 2][0]     = r0; bb[pj * 2][1]     = r1;
                    bb[pj * 2 + 1][0] = r2; bb[pj * 2 + 1][1] = r3;
                }

#pragma unroll
                for (int mi = 0; mi < 4; mi++)
#pragma unroll
                    for (int ni = 0; ni < 4; ni++)
                        MMA_F16(acc[mi][ni], a[mi], bb[ni]);
            }
        }

        // ---- epilogue: bias + scatter
#pragma unroll
        for (int mi = 0; mi < 4; mi++) {
            int m0   = wm * 64 + mi * 16 + (lane >> 2);
            int tok0 = toks[m0];
            int tok1 = toks[m0 + 8];
#pragma unroll
            for (int ni = 0; ni < 4; ni++) {
                int col = wn * 32 + ni * 8 + 2 * (lane & 3);
                float b0 = bias_s[col], b1 = bias_s[col + 1];
                if (tok0 >= 0) {
                    float2 v = make_float2(acc[mi][ni][0] + b0, acc[mi][ni][1] + b1);
                    *reinterpret_cast<float2*>(out + (size_t)tok0 * DIM_O + n0 + col) = v;
                }
                if (tok1 >= 0) {
                    float2 v = make_float2(acc[mi][ni][2] + b0, acc[mi][ni][3] + b1);
                    *reinterpret_cast<float2*>(out + (size_t)tok1 * DIM_O + n0 + col) = v;
                }
            }
        }
    }

    // ================= exit: last block resets all counters ==================
    __syncthreads();
    if (tid == 0) {
        __threadfence();
        int old = atomicAdd(&g_exit, 1);
        if (old == NBLK - 1) {
            g_setup_done = 0; g_tk_conv = 0; g_xdone = 0;
            g_tk_gemm = 0; g_exit = 0;
            for (int c = 0; c < N_CAT; c++) g_wdone[c] = 0;
            __threadfence();
        }
    }
}

// ---------------- launch --------------------------------------------------------
extern "C" void kernel_launch(void* const* d_in, const int* in_sizes, int n_in,
                              void* d_out, int out_size) {
    const float* x    = (const float*)d_in[0];   // [T, D] fp32
    const int*   cid  = (const int*)d_in[1];     // [T] int32
    const float* wgt  = (const float*)d_in[2];   // [C, D, O] fp32
    const float* bias = (const float*)d_in[3];   // [C, O] fp32
    float*       out  = (float*)d_out;           // [T, O] fp32

    (void)in_sizes; (void)n_in; (void)out_size;

    cudaFuncSetAttribute(k_persist, cudaFuncAttributeMaxDynamicSharedMemorySize, SMEM_TOTAL);

    k_persist<<<NBLK, 256, SMEM_TOTAL>>>(cid, wgt, x, bias, out);
}

// round 16
// speedup vs baseline: 1.8545x; 1.0932x over previous
#include <cuda_runtime.h>
#include <cuda_fp16.h>
#include <cstdint>

// Problem constants (fixed by dataset: B=4, S=2048, D=1024, O=1024, C=8)
#define T_TOK 8192
#define DIM_D 1024
#define DIM_O 1024
#define N_CAT 8

#define TM 128
#define TN 128
#define BK 64                        // K per smem stage
#define NCHUNK (DIM_D / BK)          // 16
#define MAX_TILES (T_TOK / TM + N_CAT)          // 72
#define N_CTA (MAX_TILES * (DIM_O / TN))        // 576

#define UNIT_FLOATS 16384
#define X_UNITS 512                  // 8.39M floats (X first!)
#define W_UNITS 512                  // then W, ordered by category (64/cat)
#define CONV_UNITS (X_UNITS + W_UNITS)

// ---------------- device scratch (no allocation allowed) --------------------
__device__ int g_perm[T_TOK];
__device__ int g_tile_cat[MAX_TILES];
__device__ int g_tile_row[MAX_TILES];
__device__ int g_tile_rows[MAX_TILES];
__device__ int g_n_tiles;

// progress state (zero at module load; reset by last exiting CTA each launch)
__device__ int g_setup_done;
__device__ int g_tk_conv;
__device__ int g_xdone;
__device__ int g_wdone[N_CAT];
__device__ int g_exit;

// fp16 operands. X in NATURAL token order (+TM zero pad rows, never written).
__device__ __half g_Xh[(T_TOK + TM) * DIM_D];
__device__ __half g_Wh[N_CAT * DIM_D * DIM_O];   // [c][d][o]

// ---------------- PTX helpers (baseline sm_70/75/80 features only) ----------
__device__ __forceinline__ uint32_t smem_u32(const void* p) {
    uint32_t a;
    asm("{ .reg .u64 t; cvta.to.shared.u64 t, %1; cvt.u32.u64 %0, t; }" : "=r"(a) : "l"(p));
    return a;
}

__device__ __forceinline__ int ld_acq(const int* p) {
    int v;
    asm volatile("ld.acquire.gpu.s32 %0, [%1];" : "=r"(v) : "l"(p) : "memory");
    return v;
}

#define CP_ASYNC16(dst, src) \
    asm volatile("cp.async.cg.shared.global [%0], [%1], 16;" :: "r"(dst), "l"(src) : "memory")
#define CP_COMMIT() asm volatile("cp.async.commit_group;" ::: "memory")
#define CP_WAIT0()  asm volatile("cp.async.wait_group 0;" ::: "memory")
#define CP_WAIT1()  asm volatile("cp.async.wait_group 1;" ::: "memory")

#define LDSM4(r0, r1, r2, r3, addr)                                              \
    asm volatile("ldmatrix.sync.aligned.m8n8.x4.shared.b16 {%0,%1,%2,%3}, [%4];" \
                 : "=r"(r0), "=r"(r1), "=r"(r2), "=r"(r3) : "r"(addr))

#define LDSM4T(r0, r1, r2, r3, addr)                                                   \
    asm volatile("ldmatrix.sync.aligned.m8n8.x4.trans.shared.b16 {%0,%1,%2,%3}, [%4];" \
                 : "=r"(r0), "=r"(r1), "=r"(r2), "=r"(r3) : "r"(addr))

#define MMA_F16(c, a, b)                                                         \
    asm volatile("mma.sync.aligned.m16n8k16.row.col.f32.f16.f16.f32 "            \
                 "{%0,%1,%2,%3}, {%4,%5,%6,%7}, {%8,%9}, {%0,%1,%2,%3};"         \
                 : "+f"((c)[0]), "+f"((c)[1]), "+f"((c)[2]), "+f"((c)[3])        \
                 : "r"((a)[0]), "r"((a)[1]), "r"((a)[2]), "r"((a)[3]),           \
                   "r"((b)[0]), "r"((b)[1]))

__device__ __forceinline__ uint32_t sw128(uint32_t off) {
    return off ^ ((off >> 3) & 0x70);
}

// smem layout for the GEMM phase (setup reuses the same dynamic smem)
#define SM_TOKS   0
#define SM_BIAS   512
#define SM_STAGE  2048
#define PART_A_BYTES 16384
#define STAGE_BYTES  32768
#define NSTAGE 3
#define SMEM_TOTAL (SM_STAGE + NSTAGE * STAGE_BYTES)

// ---------------- fused kernel: R13 grid + conv-preamble tickets -------------
__global__ __launch_bounds__(256, 2)
void k_all(const int* __restrict__ cid,
           const float* __restrict__ w,
           const float* __restrict__ x,
           const float* __restrict__ bias,
           float* __restrict__ out) {
    extern __shared__ char smem[];
    __shared__ int s_tk;
    const int tid = threadIdx.x;    // 256
    const int bid = blockIdx.y * gridDim.x + blockIdx.x;
    const uint32_t sm = smem_u32(smem);

    // ================= setup (flat block 0 only) =============================
    if (bid == 0) {
        int (*s_cnt)[256] = reinterpret_cast<int (*)[256]>(smem);          // 8KB
        int (*s_exc)[256] = reinterpret_cast<int (*)[256]>(smem + 8192);   // 8KB
        int* s_base       = reinterpret_cast<int*>(smem + 16384);

        int cl[32];
        uint32_t p0 = 0, p1 = 0;
#pragma unroll
        for (int i = 0; i < 32; i++) {
            int c = cid[tid + i * 256] & (N_CAT - 1);
            cl[i] = c;
            if (c < 4) p0 += 1u << (c * 8); else p1 += 1u << ((c - 4) * 8);
        }
#pragma unroll
        for (int c = 0; c < 4; c++) {
            s_cnt[c][tid]     = (p0 >> (c * 8)) & 0xFF;
            s_cnt[c + 4][tid] = (p1 >> (c * 8)) & 0xFF;
        }
        __syncthreads();

        const int wd = tid >> 5, lane = tid & 31;
        {
            int run = 0;
#pragma unroll
            for (int ch = 0; ch < 8; ch++) {
                int v0 = s_cnt[wd][ch * 32 + lane];
                int v = v0;
#pragma unroll
                for (int o = 1; o < 32; o <<= 1) {
                    int n = __shfl_up_sync(0xFFFFFFFFu, v, o);
                    if (lane >= o) v += n;
                }
                s_exc[wd][ch * 32 + lane] = run + v - v0;
                run += __shfl_sync(0xFFFFFFFFu, v, 31);
            }
            if (lane == 0) s_base[wd] = run;
        }
        __syncthreads();

        if (tid == 0) {
            int off = 0, nt = 0;
            for (int c = 0; c < N_CAT; c++) {
                int cnt = s_base[c];
                s_base[c] = off;
                for (int r = 0; r < cnt; r += TM) {
                    g_tile_cat[nt]  = c;
                    g_tile_row[nt]  = off + r;
                    g_tile_rows[nt] = (cnt - r < TM) ? (cnt - r) : TM;
                    nt++;
                }
                off += cnt;
            }
            g_n_tiles = nt;
        }
        __syncthreads();

        p0 = 0; p1 = 0;
#pragma unroll
        for (int i = 0; i < 32; i++) {
            int c = cl[i];
            int run = (c < 4) ? ((p0 >> (c * 8)) & 0xFF) : ((p1 >> ((c - 4) * 8)) & 0xFF);
            g_perm[s_base[c] + s_exc[c][tid] + run] = tid + i * 256;
            if (c < 4) p0 += 1u << (c * 8); else p1 += 1u << ((c - 4) * 8);
        }

        __threadfence();
        __syncthreads();
        if (tid == 0) atomicExch(&g_setup_done, 1);
        __syncthreads();
    }

    // ================= conv preamble: drain ticket pool ======================
    // X tickets first (0..511), then W ordered by category (512..1023).
    for (;;) {
        if (tid == 0) s_tk = atomicAdd(&g_tk_conv, 1);
        __syncthreads();
        const int u = s_tk;
        if (u >= CONV_UNITS) break;

        const float* src = (u < X_UNITS) ? x + (size_t)u * UNIT_FLOATS
                                         : w + (size_t)(u - X_UNITS) * UNIT_FLOATS;
        __half* dst = (u < X_UNITS) ? g_Xh + (size_t)u * UNIT_FLOATS
                                    : g_Wh + (size_t)(u - X_UNITS) * UNIT_FLOATS;
#pragma unroll 4
        for (int j = 0; j < 16; j++) {
            const size_t i = (size_t)(j * 256 + tid) * 4;
            float4 v = *reinterpret_cast<const float4*>(src + i);
            __half2 h0 = __floats2half2_rn(v.x, v.y);
            __half2 h1 = __floats2half2_rn(v.z, v.w);
            uint2 uu;
            uu.x = *reinterpret_cast<uint32_t*>(&h0);
            uu.y = *reinterpret_cast<uint32_t*>(&h1);
            *reinterpret_cast<uint2*>(dst + i) = uu;
        }
        __threadfence();
        __syncthreads();
        if (tid == 0) {
            if (u < X_UNITS) atomicAdd(&g_xdone, 1);
            else             atomicAdd(&g_wdone[(u - X_UNITS) >> 6], 1);
        }
    }

    // ================= GEMM: fixed tile per CTA (R13 scheduling) =============
    const int tile = blockIdx.x;
    const int n0   = blockIdx.y * TN;

    while (ld_acq(&g_setup_done) == 0) __nanosleep(64);

    if (tile < g_n_tiles) {
        const int cat       = g_tile_cat[tile] & (N_CAT - 1);
        const int row_start = g_tile_row[tile];
        const int rows      = g_tile_rows[tile];

        // wait: all X converted + this category's W converted
        while (ld_acq(&g_xdone) < X_UNITS) __nanosleep(64);
        while (ld_acq(&g_wdone[cat]) < 64) __nanosleep(64);
        __syncthreads();   // publish acquire to all threads

        const int wid  = tid >> 5;
        const int lane = tid & 31;
        const int wm   = wid >> 2;        // 0..1 -> m offset wm*64
        const int wn   = wid & 3;         // 0..3 -> n offset wn*32

        int*   toks   = reinterpret_cast<int*>(smem + SM_TOKS);
        float* bias_s = reinterpret_cast<float*>(smem + SM_BIAS);
        if (tid < TM) toks[tid] = (tid < rows) ? g_perm[row_start + tid] : -1;
        if (tid >= 128) bias_s[tid - 128] = bias[cat * DIM_O + n0 + tid - 128];
        __syncthreads();

        // A row pointers (gathered; chunk-invariant). Padding -> zero pad row.
        const char* aRow[4];
#pragma unroll
        for (int t = 0; t < 4; t++) {
            int r   = (tid >> 3) + t * 32;
            int tok = toks[r];
            if (tok < 0) tok = T_TOK + r;
            aRow[t] = reinterpret_cast<const char*>(g_Xh) + (size_t)tok * 2048 + (tid & 7) * 16;
        }
        const char* gB = reinterpret_cast<const char*>(g_Wh) + (((size_t)cat << 20) + n0) * 2;

#define ISSUE_CHUNK(kc, buf)                                                        \
    _Pragma("unroll")                                                               \
    for (int q = 0; q < 8; q++) {                                                   \
        uint32_t stg = sm + SM_STAGE + (buf) * STAGE_BYTES;                         \
        if (q < 4) {                                                                \
            int r = (tid >> 3) + q * 32, c = tid & 7;                               \
            const char* srcp = aRow[q] + (size_t)(kc) * 128;                        \
            CP_ASYNC16(stg + sw128((uint32_t)(r * 128 + c * 16)), srcp);            \
        } else {                                                                    \
            int i2 = tid + (q - 4) * 256;                                           \
            int r = i2 >> 4, c = i2 & 15;                                           \
            const char* srcp = gB + (size_t)((kc) * BK + r) * 2048 + c * 16;        \
            CP_ASYNC16(stg + PART_A_BYTES + (uint32_t)(r * 256 + ((c ^ (r & 7)) * 16)), srcp); \
        }                                                                           \
    }                                                                               \
    CP_COMMIT();

        float acc[4][4][4];
#pragma unroll
        for (int i = 0; i < 4; i++)
#pragma unroll
            for (int j = 0; j < 4; j++)
#pragma unroll
                for (int k = 0; k < 4; k++) acc[i][j][k] = 0.f;

        ISSUE_CHUNK(0, 0);
        ISSUE_CHUNK(1, 1);

        const int fr_row = lane & 15;
        const int fr_kb  = lane >> 4;
        const int bk_loc = (lane & 7) + ((lane >> 3) & 1) * 8;
        const int bn_blk = (lane >> 4);

        for (int it = 0; it < NCHUNK; it++) {
            if (it < NCHUNK - 1) { CP_WAIT1(); } else { CP_WAIT0(); }
            __syncthreads();

            if (it + 2 < NCHUNK) { ISSUE_CHUNK(it + 2, (it + 2) % NSTAGE); }

            const uint32_t st  = sm + SM_STAGE + (it % NSTAGE) * STAGE_BYTES;
            const uint32_t stA = st;
            const uint32_t stB = st + PART_A_BYTES;

#pragma unroll
            for (int ks = 0; ks < 4; ks++) {
                const uint32_t kcol = (uint32_t)((ks * 2 + fr_kb) * 16);

                uint32_t a[4][4], bb[4][2];
#pragma unroll
                for (int mi = 0; mi < 4; mi++) {
                    uint32_t ad = sw128((uint32_t)((wm * 64 + mi * 16 + fr_row) * 128) + kcol);
                    LDSM4(a[mi][0], a[mi][1], a[mi][2], a[mi][3], stA + ad);
                }
#pragma unroll
                for (int pj = 0; pj < 2; pj++) {
                    int k   = ks * 16 + bk_loc;
                    int blk = wn * 4 + pj * 2 + bn_blk;
                    uint32_t ad = (uint32_t)(k * 256 + ((blk ^ (k & 7)) * 16));
                    uint32_t r0, r1, r2, r3;
                    LDSM4T(r0, r1, r2, r3, stB + ad);
                    bb[pj * 2][0]     = r0; bb[pj * 2][1]     = r1;
                    bb[pj * 2 + 1][0] = r2; bb[pj * 2 + 1][1] = r3;
                }

#pragma unroll
                for (int mi = 0; mi < 4; mi++)
#pragma unroll
                    for (int ni = 0; ni < 4; ni++)
                        MMA_F16(acc[mi][ni], a[mi], bb[ni]);
            }
        }

        // ---- epilogue: bias + scatter
#pragma unroll
        for (int mi = 0; mi < 4; mi++) {
            int m0   = wm * 64 + mi * 16 + (lane >> 2);
            int tok0 = toks[m0];
            int tok1 = toks[m0 + 8];
#pragma unroll
            for (int ni = 0; ni < 4; ni++) {
                int col = wn * 32 + ni * 8 + 2 * (lane & 3);
                float b0 = bias_s[col], b1 = bias_s[col + 1];
                if (tok0 >= 0) {
                    float2 v = make_float2(acc[mi][ni][0] + b0, acc[mi][ni][1] + b1);
                    *reinterpret_cast<float2*>(out + (size_t)tok0 * DIM_O + n0 + col) = v;
                }
                if (tok1 >= 0) {
                    float2 v = make_float2(acc[mi][ni][2] + b0, acc[mi][ni][3] + b1);
                    *reinterpret_cast<float2*>(out + (size_t)tok1 * DIM_O + n0 + col) = v;
                }
            }
        }
    }

    // ================= exit: last CTA resets all counters ====================
    __syncthreads();
    if (tid == 0) {
        __threadfence();
        int old = atomicAdd(&g_exit, 1);
        if (old == N_CTA - 1) {
            g_setup_done = 0; g_tk_conv = 0; g_xdone = 0; g_exit = 0;
            for (int c = 0; c < N_CAT; c++) g_wdone[c] = 0;
            __threadfence();
        }
    }
}

// ---------------- launch --------------------------------------------------------
extern "C" void kernel_launch(void* const* d_in, const int* in_sizes, int n_in,
                              void* d_out, int out_size) {
    const float* x    = (const float*)d_in[0];   // [T, D] fp32
    const int*   cid  = (const int*)d_in[1];     // [T] int32
    const float* wgt  = (const float*)d_in[2];   // [C, D, O] fp32
    const float* bias = (const float*)d_in[3];   // [C, O] fp32
    float*       out  = (float*)d_out;           // [T, O] fp32

    (void)in_sizes; (void)n_in; (void)out_size;

    cudaFuncSetAttribute(k_all, cudaFuncAttributeMaxDynamicSharedMemorySize, SMEM_TOTAL);

    dim3 grid(MAX_TILES, DIM_O / TN);   // 72 x 8 = 576 CTAs, R13 scheduling
    k_all<<<grid, 256, SMEM_TOTAL>>>(cid, wgt, x, bias, out);
}

// round 17
// speedup vs baseline: 2.2648x; 1.2212x over previous
#include <cuda_runtime.h>
#include <cuda_fp16.h>
#include <cstdint>

// Problem constants (fixed by dataset: B=4, S=2048, D=1024, O=1024, C=8)
#define T_TOK 8192
#define DIM_D 1024
#define DIM_O 1024
#define N_CAT 8

#define TM 128
#define TN 128
#define BK 64                        // K per smem stage
#define NCHUNK (DIM_D / BK)          // 16
#define MAX_TILES (T_TOK / TM + N_CAT)

// ---------------- device scratch (no allocation allowed) --------------------
__device__ int g_perm[T_TOK];
__device__ int g_tile_cat[MAX_TILES];
__device__ int g_tile_row[MAX_TILES];
__device__ int g_tile_rows[MAX_TILES];
__device__ int g_n_tiles;

// fp16 operands. X in NATURAL token order (+TM zero pad rows for partial
// tiles; never written -> stay zero from module init). W in NATIVE [c][d][o].
__device__ __half g_Xh[(T_TOK + TM) * DIM_D];
__device__ __half g_Wh[N_CAT * DIM_D * DIM_O];

// ---------------- PTX helpers (baseline sm_80/75 features only) -------------
__device__ __forceinline__ uint32_t smem_u32(const void* p) {
    uint32_t a;
    asm("{ .reg .u64 t; cvta.to.shared.u64 t, %1; cvt.u32.u64 %0, t; }" : "=r"(a) : "l"(p));
    return a;
}

#define CP_ASYNC16(dst, src) \
    asm volatile("cp.async.cg.shared.global [%0], [%1], 16;" :: "r"(dst), "l"(src) : "memory")
#define CP_COMMIT() asm volatile("cp.async.commit_group;" ::: "memory")
#define CP_WAIT0()  asm volatile("cp.async.wait_group 0;" ::: "memory")
#define CP_WAIT1()  asm volatile("cp.async.wait_group 1;" ::: "memory")

#define LDSM4(r0, r1, r2, r3, addr)                                              \
    asm volatile("ldmatrix.sync.aligned.m8n8.x4.shared.b16 {%0,%1,%2,%3}, [%4];" \
                 : "=r"(r0), "=r"(r1), "=r"(r2), "=r"(r3) : "r"(addr))

#define LDSM4T(r0, r1, r2, r3, addr)                                                   \
    asm volatile("ldmatrix.sync.aligned.m8n8.x4.trans.shared.b16 {%0,%1,%2,%3}, [%4];" \
                 : "=r"(r0), "=r"(r1), "=r"(r2), "=r"(r3) : "r"(addr))

#define MMA_F16(c, a, b)                                                         \
    asm volatile("mma.sync.aligned.m16n8k16.row.col.f32.f16.f16.f32 "            \
                 "{%0,%1,%2,%3}, {%4,%5,%6,%7}, {%8,%9}, {%0,%1,%2,%3};"         \
                 : "+f"((c)[0]), "+f"((c)[1]), "+f"((c)[2]), "+f"((c)[3])        \
                 : "r"((a)[0]), "r"((a)[1]), "r"((a)[2]), "r"((a)[3]),           \
                   "r"((b)[0]), "r"((b)[1]))

__device__ __forceinline__ uint32_t sw128(uint32_t off) {
    return off ^ ((off >> 3) & 0x70);
}

// ---------------- single prologue kernel ------------------------------------
// block 0:             setup (atomic-free counting sort + tile descriptors)
// blocks [1, 4096]:    W stream convert fp32->fp16 (2048 elems/block)
// blocks (4096, 8192]: X stream convert fp32->fp16 (2048 elems/block)
// fp32 source reads use __ldcs (evict-first): read-once data must not evict
// the fp16 outputs that the GEMM immediately re-reads from L2.
__global__ void k_prep(const int* __restrict__ cid,
                       const float* __restrict__ w,
                       const float* __restrict__ x) {
    __shared__ int s_cnt[N_CAT][256];
    __shared__ int s_exc[N_CAT][256];
    __shared__ int s_base[N_CAT];

    const int b   = blockIdx.x;
    const int tid = threadIdx.x;    // 256

    if (b == 0) {
        // ---- load 32 cids/thread, count into packed 8-bit lanes
        int cl[32];
        uint32_t p0 = 0, p1 = 0;
#pragma unroll
        for (int i = 0; i < 32; i++) {
            int c = cid[tid + i * 256] & (N_CAT - 1);
            cl[i] = c;
            if (c < 4) p0 += 1u << (c * 8); else p1 += 1u << ((c - 4) * 8);
        }
#pragma unroll
        for (int c = 0; c < 4; c++) {
            s_cnt[c][tid]     = (p0 >> (c * 8)) & 0xFF;
            s_cnt[c + 4][tid] = (p1 >> (c * 8)) & 0xFF;
        }
        __syncthreads();

        // ---- 8 warps: exclusive scan of 256 counts (one category each)
        const int wid = tid >> 5, lane = tid & 31;
        {
            int run = 0;
#pragma unroll
            for (int ch = 0; ch < 8; ch++) {
                int v0 = s_cnt[wid][ch * 32 + lane];
                int v = v0;
#pragma unroll
                for (int o = 1; o < 32; o <<= 1) {
                    int n = __shfl_up_sync(0xFFFFFFFFu, v, o);
                    if (lane >= o) v += n;
                }
                s_exc[wid][ch * 32 + lane] = run + v - v0;
                run += __shfl_sync(0xFFFFFFFFu, v, 31);
            }
            if (lane == 0) s_base[wid] = run;   // temp: per-cat totals
        }
        __syncthreads();

        // ---- thread 0: base offsets + tile descriptors
        if (tid == 0) {
            int off = 0, nt = 0;
            for (int c = 0; c < N_CAT; c++) {
                int cnt = s_base[c];
                s_base[c] = off;
                for (int r = 0; r < cnt; r += TM) {
                    g_tile_cat[nt]  = c;
                    g_tile_row[nt]  = off + r;
                    g_tile_rows[nt] = (cnt - r < TM) ? (cnt - r) : TM;
                    nt++;
                }
                off += cnt;
            }
            g_n_tiles = nt;
        }
        __syncthreads();

        // ---- place tokens: pos = base[c] + exc[c][tid] + running local rank
        p0 = 0; p1 = 0;
#pragma unroll
        for (int i = 0; i < 32; i++) {
            int c = cl[i];
            int run = (c < 4) ? ((p0 >> (c * 8)) & 0xFF) : ((p1 >> ((c - 4) * 8)) & 0xFF);
            g_perm[s_base[c] + s_exc[c][tid] + run] = tid + i * 256;
            if (c < 4) p0 += 1u << (c * 8); else p1 += 1u << ((c - 4) * 8);
        }
    } else if (b <= 4096) {
        // W: 2048 fp32/block (2 float4 per thread), evict-first reads
        const size_t base = (size_t)(b - 1) * 2048;
#pragma unroll
        for (int j = 0; j < 2; j++) {
            const size_t i = base + (size_t)(tid + j * 256) * 4;
            float4 v = __ldcs(reinterpret_cast<const float4*>(w + i));
            __half2 h0 = __floats2half2_rn(v.x, v.y);
            __half2 h1 = __floats2half2_rn(v.z, v.w);
            uint2 u;
            u.x = *reinterpret_cast<uint32_t*>(&h0);
            u.y = *reinterpret_cast<uint32_t*>(&h1);
            *reinterpret_cast<uint2*>(&g_Wh[i]) = u;
        }
    } else {
        // X: 2048 fp32/block (4096 blocks cover 8192x1024), evict-first reads
        const size_t base = (size_t)(b - 4097) * 2048;
#pragma unroll
        for (int j = 0; j < 2; j++) {
            const size_t i = base + (size_t)(tid + j * 256) * 4;
            float4 v = __ldcs(reinterpret_cast<const float4*>(x + i));
            __half2 h0 = __floats2half2_rn(v.x, v.y);
            __half2 h1 = __floats2half2_rn(v.z, v.w);
            uint2 u;
            u.x = *reinterpret_cast<uint32_t*>(&h0);
            u.y = *reinterpret_cast<uint32_t*>(&h1);
            *reinterpret_cast<uint2*>(&g_Xh[i]) = u;
        }
    }
}

// ---------------- fp16 mma.sync grouped GEMM --------------------------------
// smem: [0..512) toks, [512..1024) bias, [2048..) 3 stages of
// {A: 128 rows x 128B (sw128) | B: 64 k-rows x 256B (xor-8 16B-block swizzle)}
#define SM_TOKS   0
#define SM_BIAS   512
#define SM_STAGE  2048
#define PART_A_BYTES 16384
#define STAGE_BYTES  32768
#define NSTAGE 3
#define SMEM_TOTAL (SM_STAGE + NSTAGE * STAGE_BYTES)

__global__ __launch_bounds__(256, 2)
void k_gemm_f16(const float* __restrict__ bias, float* __restrict__ out) {
    const int tile = blockIdx.x;
    if (tile >= g_n_tiles) return;

    const int cat       = g_tile_cat[tile] & (N_CAT - 1);
    const int row_start = g_tile_row[tile];
    const int rows      = g_tile_rows[tile];
    const int n0        = blockIdx.y * TN;

    extern __shared__ char smem[];
    const uint32_t sm = smem_u32(smem);
    const int tid  = threadIdx.x;
    const int wid  = tid >> 5;
    const int lane = tid & 31;
    const int wm   = wid >> 2;        // 0..1 -> m offset wm*64
    const int wn   = wid & 3;         // 0..3 -> n offset wn*32

    int*   toks   = reinterpret_cast<int*>(smem + SM_TOKS);
    float* bias_s = reinterpret_cast<float*>(smem + SM_BIAS);
    if (tid < TM) toks[tid] = (tid < rows) ? g_perm[row_start + tid] : -1;
    if (tid >= 128) bias_s[tid - 128] = bias[cat * DIM_O + n0 + tid - 128];
    __syncthreads();   // toks needed by every thread's A row pointers

    // A row pointers (gathered; chunk-invariant). Padding -> zero pad row.
    const char* aRow[4];
#pragma unroll
    for (int t = 0; t < 4; t++) {
        int r   = (tid >> 3) + t * 32;
        int tok = toks[r];
        if (tok < 0) tok = T_TOK + r;   // zero pad row
        aRow[t] = reinterpret_cast<const char*>(g_Xh) + (size_t)tok * 2048 + (tid & 7) * 16;
    }
    const char* gB = reinterpret_cast<const char*>(g_Wh) + (((size_t)cat << 20) + n0) * 2;

    // chunk loader: A 128 rows x 8 x 16B + B 64 k-rows x 16 x 16B = 2048, 8/thread
#define ISSUE_CHUNK(kc, buf)                                                        \
    _Pragma("unroll")                                                               \
    for (int t = 0; t < 8; t++) {                                                   \
        uint32_t stg = sm + SM_STAGE + (buf) * STAGE_BYTES;                         \
        if (t < 4) {                                                                \
            int r = (tid >> 3) + t * 32, c = tid & 7;                               \
            const char* src = aRow[t] + (size_t)(kc) * 128;                         \
            CP_ASYNC16(stg + sw128((uint32_t)(r * 128 + c * 16)), src);             \
        } else {                                                                    \
            int i2 = tid + (t - 4) * 256;                                           \
            int r = i2 >> 4, c = i2 & 15;    /* r = k row 0..63, c = 16B block */   \
            const char* src = gB + (size_t)((kc) * BK + r) * 2048 + c * 16;         \
            CP_ASYNC16(stg + PART_A_BYTES + (uint32_t)(r * 256 + ((c ^ (r & 7)) * 16)), src); \
        }                                                                           \
    }                                                                               \
    CP_COMMIT();

    float acc[4][4][4];
#pragma unroll
    for (int i = 0; i < 4; i++)
#pragma unroll
        for (int j = 0; j < 4; j++)
#pragma unroll
            for (int k = 0; k < 4; k++) acc[i][j][k] = 0.f;

    ISSUE_CHUNK(0, 0);
    ISSUE_CHUNK(1, 1);

    const int fr_row = lane & 15;
    const int fr_kb  = lane >> 4;
    const int bk_loc = (lane & 7) + ((lane >> 3) & 1) * 8;   // 0..15
    const int bn_blk = (lane >> 4);                           // 0/1 -> +8 n

    for (int it = 0; it < NCHUNK; it++) {
        if (it < NCHUNK - 1) { CP_WAIT1(); } else { CP_WAIT0(); }
        __syncthreads();

        if (it + 2 < NCHUNK) { ISSUE_CHUNK(it + 2, (it + 2) % NSTAGE); }

        const uint32_t st  = sm + SM_STAGE + (it % NSTAGE) * STAGE_BYTES;
        const uint32_t stA = st;
        const uint32_t stB = st + PART_A_BYTES;

#pragma unroll
        for (int ks = 0; ks < 4; ks++) {
            const uint32_t kcol = (uint32_t)((ks * 2 + fr_kb) * 16);

            uint32_t a[4][4], b[4][2];
#pragma unroll
            for (int mi = 0; mi < 4; mi++) {
                uint32_t ad = sw128((uint32_t)((wm * 64 + mi * 16 + fr_row) * 128) + kcol);
                LDSM4(a[mi][0], a[mi][1], a[mi][2], a[mi][3], stA + ad);
            }
#pragma unroll
            for (int pj = 0; pj < 2; pj++) {
                int k   = ks * 16 + bk_loc;
                int blk = wn * 4 + pj * 2 + bn_blk;
                uint32_t ad = (uint32_t)(k * 256 + ((blk ^ (k & 7)) * 16));
                uint32_t r0, r1, r2, r3;
                LDSM4T(r0, r1, r2, r3, stB + ad);
                b[pj * 2][0]     = r0; b[pj * 2][1]     = r1;
                b[pj * 2 + 1][0] = r2; b[pj * 2 + 1][1] = r3;
            }

#pragma unroll
            for (int mi = 0; mi < 4; mi++)
#pragma unroll
                for (int ni = 0; ni < 4; ni++)
                    MMA_F16(acc[mi][ni], a[mi], b[ni]);
        }
    }

    // ---- epilogue: bias + scatter
#pragma unroll
    for (int mi = 0; mi < 4; mi++) {
        int m0   = wm * 64 + mi * 16 + (lane >> 2);
        int tok0 = toks[m0];
        int tok1 = toks[m0 + 8];
#pragma unroll
        for (int ni = 0; ni < 4; ni++) {
            int col = wn * 32 + ni * 8 + 2 * (lane & 3);
            float b0 = bias_s[col], b1 = bias_s[col + 1];
            if (tok0 >= 0) {
                float2 v = make_float2(acc[mi][ni][0] + b0, acc[mi][ni][1] + b1);
                *reinterpret_cast<float2*>(out + (size_t)tok0 * DIM_O + n0 + col) = v;
            }
            if (tok1 >= 0) {
                float2 v = make_float2(acc[mi][ni][2] + b0, acc[mi][ni][3] + b1);
                *reinterpret_cast<float2*>(out + (size_t)tok1 * DIM_O + n0 + col) = v;
            }
        }
    }
}

// ---------------- launch --------------------------------------------------------
extern "C" void kernel_launch(void* const* d_in, const int* in_sizes, int n_in,
                              void* d_out, int out_size) {
    const float* x    = (const float*)d_in[0];   // [T, D] fp32
    const int*   cid  = (const int*)d_in[1];     // [T] int32
    const float* wgt  = (const float*)d_in[2];   // [C, D, O] fp32
    const float* bias = (const float*)d_in[3];   // [C, O] fp32
    float*       out  = (float*)d_out;           // [T, O] fp32

    (void)in_sizes; (void)n_in; (void)out_size;

    cudaFuncSetAttribute(k_gemm_f16, cudaFuncAttributeMaxDynamicSharedMemorySize, SMEM_TOTAL);

    // 1 setup block + 4096 W-convert blocks + 4096 X-convert blocks
    k_prep<<<8193, 256>>>(cid, wgt, x);

    dim3 grid(MAX_TILES, DIM_O / TN);   // 72 x 8; CTAs past g_n_tiles exit early
    k_gemm_f16<<<grid, 256, SMEM_TOTAL>>>(bias, out);
}